// round 14
// baseline (speedup 1.0000x reference)
#include <cuda_runtime.h>
#include <cuda_fp16.h>
#include <math.h>
#include <stdint.h>

// Problem constants
#define BB 16384
#define NN_ 20
#define NODE_DIM 172
#define EDGE_DIM 172
#define TIME_DIM 100
#define HH 4
#define OUT_DIM 272
#define KEY_DIM 444
#define DH 68
#define EPS_LN 1e-5f
#define SCALE_QK 0.12126781251816648f   // 68^-0.5

// Scratch (device globals)
__device__ __half g_QIN[BB * OUT_DIM];
__device__ __half g_Q[BB * OUT_DIM];
__device__ __half g_QW[BB * HH * KEY_DIM];        // [B,1776]
__device__ __half g_WS[BB * HH * KEY_DIM];        // [B,1776]
__device__ __half g_ATT[BB * OUT_DIM];
__device__ float  g_X[BB * OUT_DIM];
__device__ __half g_Wq[OUT_DIM * OUT_DIM];
__device__ __half g_Wr[OUT_DIM * OUT_DIM];
__device__ __half g_Bt2[HH * KEY_DIM * OUT_DIM];  // [1776,272] block-diag scale*Wk^T
__device__ __half g_Bt3[OUT_DIM * HH * KEY_DIM];  // [272,1776] block-diag Wv

// ---------------------------------------------------------------------------
// helpers
// ---------------------------------------------------------------------------
__device__ __forceinline__ void mma_fp16(float (&c)[4], const uint32_t (&a)[4],
                                         const uint32_t (&b)[2]) {
    asm volatile(
        "mma.sync.aligned.m16n8k16.row.col.f32.f16.f16.f32 "
        "{%0,%1,%2,%3}, {%4,%5,%6,%7}, {%8,%9}, {%0,%1,%2,%3};"
        : "+f"(c[0]), "+f"(c[1]), "+f"(c[2]), "+f"(c[3])
        : "r"(a[0]), "r"(a[1]), "r"(a[2]), "r"(a[3]), "r"(b[0]), "r"(b[1]));
}

__device__ __forceinline__ void ldsm_x4(uint32_t (&r)[4], uint32_t addr) {
    asm volatile("ldmatrix.sync.aligned.m8n8.x4.shared.b16 {%0,%1,%2,%3}, [%4];"
        : "=r"(r[0]), "=r"(r[1]), "=r"(r[2]), "=r"(r[3]) : "r"(addr));
}

__device__ __forceinline__ void cp16z(uint32_t d, const void* s, int sz) {
    asm volatile("cp.async.cg.shared.global [%0], [%1], 16, %2;"
                 :: "r"(d), "l"(s), "r"(sz));
}
__device__ __forceinline__ void cp_commit() {
    asm volatile("cp.async.commit_group;");
}
template<int W> __device__ __forceinline__ void cp_wait() {
    asm volatile("cp.async.wait_group %0;" :: "n"(W));
}

// ---------------------------------------------------------------------------
// Prep kernels
// ---------------------------------------------------------------------------
#define PW (OUT_DIM * OUT_DIM)              // 73984
#define PB (HH * KEY_DIM * OUT_DIM)         // 483072
#define PQ (BB * OUT_DIM)                   // 4456448
#define W0 PW
#define W1 (W0 + PW)
#define W2 (W1 + PB)
#define W3 (W2 + PB)

__global__ void prep_w(const float* __restrict__ Wq, const float* __restrict__ Wr,
                       const float* __restrict__ Wk, const float* __restrict__ Wv,
                       __half* __restrict__ dWq, __half* __restrict__ dWr,
                       __half* __restrict__ dB2, __half* __restrict__ dB3) {
    long idx = (long)blockIdx.x * 256 + threadIdx.x;
    if (idx < W0) {
        dWq[idx] = __float2half_rn(Wq[idx]);
    } else if (idx < W1) {
        long i = idx - W0;
        dWr[i] = __float2half_rn(Wr[i]);
    } else if (idx < W2) {
        long i = idx - W1;
        int n = (int)(i / OUT_DIM), k = (int)(i - (long)n * OUT_DIM);
        int h = n / KEY_DIM, j = n - h * KEY_DIM;
        float v = 0.f;
        if (k >= h * DH && k < h * DH + DH)
            v = SCALE_QK * Wk[k * KEY_DIM + j];
        dB2[i] = __float2half_rn(v);
    } else if (idx < W3) {
        long i = idx - W2;
        int n = (int)(i / (HH * KEY_DIM)), k = (int)(i - (long)n * (HH * KEY_DIM));
        int h = n / DH;
        float v = 0.f;
        if (k >= h * KEY_DIM && k < h * KEY_DIM + KEY_DIM)
            v = Wv[n * KEY_DIM + (k - h * KEY_DIM)];
        dB3[i] = __float2half_rn(v);
    }
}

__global__ void prep_qin(const float* __restrict__ node,
                         const float* __restrict__ ntime,
                         __half* __restrict__ dQIN) {
    long i = (long)blockIdx.x * 256 + threadIdx.x;
    if (i >= PQ) return;
    int b = (int)(i / OUT_DIM), o = (int)(i - (long)b * OUT_DIM);
    float v = (o < NODE_DIM) ? node[(long)b * NODE_DIM + o]
                             : ntime[(long)b * TIME_DIM + (o - NODE_DIM)];
    dQIN[i] = __float2half_rn(v);
}

// ---------------------------------------------------------------------------
// fp16 TC GEMM (cp.async 3-stage + ldmatrix):  C[m,n] = sum_k A[m,k]*Bt[n,k]
// BM=128, BN=64, BK=32, warp tile 64x32, mma.m16n8k16, fp32 accumulate.
// ---------------------------------------------------------------------------
template<int NPH, int KPH, bool HALF_C>
__global__ __launch_bounds__(128)
void gemm_fp16(const __half* __restrict__ A, int lda,
               const __half* __restrict__ Bt, int ldb,
               void* __restrict__ Cv, int ldc, int N, int K) {
    __shared__ __half As[3][128][40];
    __shared__ __half Bs[3][64][40];

    const int t = threadIdx.x;
    const int warp = t >> 5, lane = t & 31;
    const int wm = (warp >> 1) * 64, wn = (warp & 1) * 32;
    const int gid = lane >> 2, tig = lane & 3;
    const long m0 = (long)blockIdx.y * 128;
    const int n0 = blockIdx.x * 64;

    const uint32_t as_base = (uint32_t)__cvta_generic_to_shared(&As[0][0][0]);
    const uint32_t bs_base = (uint32_t)__cvta_generic_to_shared(&Bs[0][0][0]);

    int h_lo = n0 / NPH;
    int n_last = min(n0 + 64, N) - 1;
    int h_hi = n_last / NPH;
    int klo = (h_lo * KPH) & ~31;
    int khi = min((((h_hi + 1) * KPH) + 31) & ~31, (K + 31) & ~31);
    int nstage = (khi - klo) >> 5;

    float acc[4][4][4];
    #pragma unroll
    for (int mi = 0; mi < 4; mi++)
        #pragma unroll
        for (int ni = 0; ni < 4; ni++)
            #pragma unroll
            for (int q = 0; q < 4; q++) acc[mi][ni][q] = 0.f;

    auto load_stage = [&](int kk, int buf) {
        #pragma unroll
        for (int i = 0; i < 4; i++) {
            int id = i * 128 + t;
            int r = id >> 2, seg = (id & 3) * 8;
            int col = kk + seg;
            cp16z(as_base + (uint32_t)(buf * 5120 + r * 40 + seg) * 2,
                  A + (m0 + r) * lda + min(col, K - 8),
                  col < K ? 16 : 0);
        }
        #pragma unroll
        for (int i = 0; i < 2; i++) {
            int id = i * 128 + t;
            int r = id >> 2, seg = (id & 3) * 8;
            int col = kk + seg;
            int rr = n0 + r;
            cp16z(bs_base + (uint32_t)(buf * 2560 + r * 40 + seg) * 2,
                  Bt + (long)min(rr, N - 1) * ldb + min(col, K - 8),
                  (rr < N && col < K) ? 16 : 0);
        }
    };

    auto compute = [&](int buf) {
        const int lr = lane & 7, sel = lane >> 3;
        #pragma unroll
        for (int ks = 0; ks < 32; ks += 16) {
            uint32_t af[4][4];
            #pragma unroll
            for (int mi = 0; mi < 4; mi++) {
                uint32_t addr = as_base + 2u * (uint32_t)(buf * 5120 +
                    (wm + mi * 16 + (sel & 1) * 8 + lr) * 40 + ks + (sel >> 1) * 8);
                ldsm_x4(af[mi], addr);
            }
            uint32_t bp[2][4];
            #pragma unroll
            for (int p = 0; p < 2; p++) {
                uint32_t addr = bs_base + 2u * (uint32_t)(buf * 2560 +
                    (wn + p * 16 + (sel >> 1) * 8 + lr) * 40 + ks + (sel & 1) * 8);
                ldsm_x4(bp[p], addr);
            }
            #pragma unroll
            for (int ni = 0; ni < 4; ni++) {
                uint32_t bf[2] = { bp[ni >> 1][(ni & 1) * 2],
                                   bp[ni >> 1][(ni & 1) * 2 + 1] };
                #pragma unroll
                for (int mi = 0; mi < 4; mi++)
                    mma_fp16(acc[mi][ni], af[mi], bf);
            }
        }
    };

    load_stage(klo, 0);
    cp_commit();
    if (nstage > 1) { load_stage(klo + 32, 1); cp_commit(); }

    int buf = 0;
    for (int s = 0; s < nstage; s++) {
        if (s + 2 < nstage) {
            load_stage(klo + (s + 2) * 32, (s + 2) % 3);
            cp_commit();
            cp_wait<2>();
        } else if (s + 1 < nstage) {
            cp_wait<1>();
        } else {
            cp_wait<0>();
        }
        __syncthreads();
        compute(buf);
        buf = (buf + 1) % 3;
        __syncthreads();
    }

    #pragma unroll
    for (int mi = 0; mi < 4; mi++)
        #pragma unroll
        for (int ni = 0; ni < 4; ni++) {
            long r = m0 + wm + mi * 16 + gid;
            int cn = n0 + wn + ni * 8 + tig * 2;
            if (cn < N) {
                if (HALF_C) {
                    __half* C = (__half*)Cv;
                    *(__half2*)(C + r * ldc + cn) =
                        __floats2half2_rn(acc[mi][ni][0], acc[mi][ni][1]);
                    *(__half2*)(C + (r + 8) * ldc + cn) =
                        __floats2half2_rn(acc[mi][ni][2], acc[mi][ni][3]);
                } else {
                    float* C = (float*)Cv;
                    *(float2*)(C + r * ldc + cn) =
                        make_float2(acc[mi][ni][0], acc[mi][ni][1]);
                    *(float2*)(C + (r + 8) * ldc + cn) =
                        make_float2(acc[mi][ni][2], acc[mi][ni][3]);
                }
            }
        }
}

// ---------------------------------------------------------------------------
// WIDE fp16 TC GEMM for the QW projection: BM=128, BN=128, 256 threads
// (8 warps, 2x4), 2-stage cp.async, warp tile 64x32. Halves the per-A-tile
// L2 re-read count vs BN=64 (n-tiles 28 -> 14). Same k-loop order and mma
// tiling per output element => bit-identical results.
// ---------------------------------------------------------------------------
template<int NPH, int KPH>
__global__ __launch_bounds__(256)
void gemm_wide(const __half* __restrict__ A, int lda,
               const __half* __restrict__ Bt, int ldb,
               __half* __restrict__ C, int ldc, int N, int K) {
    __shared__ __half As[2][128][40];
    __shared__ __half Bs[2][128][40];

    const int t = threadIdx.x;
    const int warp = t >> 5, lane = t & 31;
    const int wm = (warp >> 2) * 64, wn = (warp & 3) * 32;
    const int gid = lane >> 2, tig = lane & 3;
    const long m0 = (long)blockIdx.y * 128;
    const int n0 = blockIdx.x * 128;

    const uint32_t as_base = (uint32_t)__cvta_generic_to_shared(&As[0][0][0]);
    const uint32_t bs_base = (uint32_t)__cvta_generic_to_shared(&Bs[0][0][0]);

    int h_lo = n0 / NPH;
    int n_last = min(n0 + 128, N) - 1;
    int h_hi = n_last / NPH;
    int klo = (h_lo * KPH) & ~31;
    int khi = min((((h_hi + 1) * KPH) + 31) & ~31, (K + 31) & ~31);
    int nstage = (khi - klo) >> 5;

    float acc[4][4][4];
    #pragma unroll
    for (int mi = 0; mi < 4; mi++)
        #pragma unroll
        for (int ni = 0; ni < 4; ni++)
            #pragma unroll
            for (int q = 0; q < 4; q++) acc[mi][ni][q] = 0.f;

    auto load_stage = [&](int kk, int buf) {
        #pragma unroll
        for (int i = 0; i < 2; i++) {        // A: 128 rows x 4 chunks
            int id = i * 256 + t;
            int r = id >> 2, seg = (id & 3) * 8;
            int col = kk + seg;
            cp16z(as_base + (uint32_t)(buf * 5120 + r * 40 + seg) * 2,
                  A + (m0 + r) * lda + min(col, K - 8),
                  col < K ? 16 : 0);
        }
        #pragma unroll
        for (int i = 0; i < 2; i++) {        // B: 128 rows x 4 chunks
            int id = i * 256 + t;
            int r = id >> 2, seg = (id & 3) * 8;
            int col = kk + seg;
            int rr = n0 + r;
            cp16z(bs_base + (uint32_t)(buf * 5120 + r * 40 + seg) * 2,
                  Bt + (long)min(rr, N - 1) * ldb + min(col, K - 8),
                  (rr < N && col < K) ? 16 : 0);
        }
    };

    auto compute = [&](int buf) {
        const int lr = lane & 7, sel = lane >> 3;
        #pragma unroll
        for (int ks = 0; ks < 32; ks += 16) {
            uint32_t af[4][4];
            #pragma unroll
            for (int mi = 0; mi < 4; mi++) {
                uint32_t addr = as_base + 2u * (uint32_t)(buf * 5120 +
                    (wm + mi * 16 + (sel & 1) * 8 + lr) * 40 + ks + (sel >> 1) * 8);
                ldsm_x4(af[mi], addr);
            }
            uint32_t bp[2][4];
            #pragma unroll
            for (int p = 0; p < 2; p++) {
                uint32_t addr = bs_base + 2u * (uint32_t)(buf * 5120 +
                    (wn + p * 16 + (sel >> 1) * 8 + lr) * 40 + ks + (sel & 1) * 8);
                ldsm_x4(bp[p], addr);
            }
            #pragma unroll
            for (int ni = 0; ni < 4; ni++) {
                uint32_t bf[2] = { bp[ni >> 1][(ni & 1) * 2],
                                   bp[ni >> 1][(ni & 1) * 2 + 1] };
                #pragma unroll
                for (int mi = 0; mi < 4; mi++)
                    mma_fp16(acc[mi][ni], af[mi], bf);
            }
        }
    };

    load_stage(klo, 0);
    cp_commit();

    int buf = 0;
    for (int s = 0; s < nstage; s++) {
        if (s + 1 < nstage) {
            load_stage(klo + (s + 1) * 32, buf ^ 1);
            cp_commit();
            cp_wait<1>();
        } else {
            cp_wait<0>();
        }
        __syncthreads();
        compute(buf);
        buf ^= 1;
        __syncthreads();
    }

    #pragma unroll
    for (int mi = 0; mi < 4; mi++)
        #pragma unroll
        for (int ni = 0; ni < 4; ni++) {
            long r = m0 + wm + mi * 16 + gid;
            int cn = n0 + wn + ni * 8 + tig * 2;
            if (cn < N) {
                *(__half2*)(C + r * ldc + cn) =
                    __floats2half2_rn(acc[mi][ni][0], acc[mi][ni][1]);
                *(__half2*)(C + (r + 8) * ldc + cn) =
                    __floats2half2_rn(acc[mi][ni][2], acc[mi][ni][3]);
            }
        }
}

// ---------------------------------------------------------------------------
// Warp-per-row SINGLE-PASS attention (frozen; __expf)
// ---------------------------------------------------------------------------
__device__ __forceinline__ float2 load_kv2(const float* pN, const float* pE,
                                           const float* pT, int j0) {
    if (j0 < NODE_DIM) return __ldg((const float2*)(pN + j0));
    if (j0 < NODE_DIM + EDGE_DIM) return __ldg((const float2*)(pE + (j0 - NODE_DIM)));
    if (j0 < KEY_DIM) return __ldg((const float2*)(pT + (j0 - NODE_DIM - EDGE_DIM)));
    return make_float2(0.f, 0.f);
}

__global__ __launch_bounds__(128, 4)
void attn_kernel(const float* __restrict__ nbN,
                 const float* __restrict__ nbT,
                 const float* __restrict__ nbE,
                 const int*   __restrict__ masks,
                 const __half* __restrict__ QW,
                 __half* __restrict__ WS) {
    const int lane = threadIdx.x & 31;
    const int warp = threadIdx.x >> 5;
    const long b = (long)blockIdx.x * 4 + warp;

    int mk = (lane < NN_) ? masks[b * NN_ + lane] : 0;
    unsigned bal = __ballot_sync(0xffffffffu, (lane < NN_) && (mk != 0));
    int nv = __popc(bal);
    const bool uni = (nv == 0);
    int map = uni ? lane : __fns(bal, 0, lane + 1);
    if (uni) nv = NN_;

    uint32_t qh[4][7];
    if (!uni) {
        const __half* qp = QW + b * (HH * KEY_DIM);
        #pragma unroll
        for (int h = 0; h < 4; h++)
            #pragma unroll
            for (int i = 0; i < 7; i++) {
                int j0 = 2 * lane + 64 * i;
                qh[h][i] = (j0 < KEY_DIM)
                    ? __ldg((const uint32_t*)(qp + h * KEY_DIM + j0)) : 0u;
            }
    }

    float2 a[4][7];
    #pragma unroll
    for (int h = 0; h < 4; h++)
        #pragma unroll
        for (int i = 0; i < 7; i++) a[h][i] = make_float2(0.f, 0.f);
    float m[4] = {-3e38f, -3e38f, -3e38f, -3e38f};
    float sum[4] = {0.f, 0.f, 0.f, 0.f};

    for (int n = 0; n < nv; n++) {
        int src = __shfl_sync(0xffffffffu, map, n);
        const float* pN = nbN + (b * NN_ + src) * NODE_DIM;
        const float* pE = nbE + (b * NN_ + src) * EDGE_DIM;
        const float* pT = nbT + (b * NN_ + src) * TIME_DIM;
        float2 kv[7];
        #pragma unroll
        for (int i = 0; i < 7; i++) kv[i] = load_kv2(pN, pE, pT, 2 * lane + 64 * i);

        if (!uni) {
            float s0 = 0.f, s1 = 0.f, s2 = 0.f, s3 = 0.f;
            #pragma unroll
            for (int i = 0; i < 7; i++) {
                float2 q0 = __half22float2(*(const __half2*)&qh[0][i]);
                float2 q1 = __half22float2(*(const __half2*)&qh[1][i]);
                float2 q2 = __half22float2(*(const __half2*)&qh[2][i]);
                float2 q3 = __half22float2(*(const __half2*)&qh[3][i]);
                s0 = fmaf(kv[i].x, q0.x, fmaf(kv[i].y, q0.y, s0));
                s1 = fmaf(kv[i].x, q1.x, fmaf(kv[i].y, q1.y, s1));
                s2 = fmaf(kv[i].x, q2.x, fmaf(kv[i].y, q2.y, s2));
                s3 = fmaf(kv[i].x, q3.x, fmaf(kv[i].y, q3.y, s3));
            }
            #pragma unroll
            for (int o = 16; o; o >>= 1) {
                s0 += __shfl_xor_sync(0xffffffffu, s0, o);
                s1 += __shfl_xor_sync(0xffffffffu, s1, o);
                s2 += __shfl_xor_sync(0xffffffffu, s2, o);
                s3 += __shfl_xor_sync(0xffffffffu, s3, o);
            }
            float sh[4] = {s0, s1, s2, s3};

            #pragma unroll
            for (int h = 0; h < 4; h++) {
                float s = sh[h];
                if (s > m[h]) {
                    float c = __expf(m[h] - s);
                    sum[h] = sum[h] * c + 1.f;
                    m[h] = s;
                    #pragma unroll
                    for (int i = 0; i < 7; i++) {
                        a[h][i].x = fmaf(a[h][i].x, c, kv[i].x);
                        a[h][i].y = fmaf(a[h][i].y, c, kv[i].y);
                    }
                } else {
                    float w = __expf(s - m[h]);
                    sum[h] += w;
                    #pragma unroll
                    for (int i = 0; i < 7; i++) {
                        a[h][i].x = fmaf(w, kv[i].x, a[h][i].x);
                        a[h][i].y = fmaf(w, kv[i].y, a[h][i].y);
                    }
                }
            }
        } else {
            #pragma unroll
            for (int i = 0; i < 7; i++) {
                a[0][i].x += kv[i].x;
                a[0][i].y += kv[i].y;
            }
        }
    }

    __half* wsp = WS + b * (HH * KEY_DIM);
    if (!uni) {
        #pragma unroll
        for (int h = 0; h < 4; h++) {
            float inv = 1.f / sum[h];
            #pragma unroll
            for (int i = 0; i < 7; i++) {
                int j0 = 2 * lane + 64 * i;
                if (j0 < KEY_DIM)
                    *(__half2*)(wsp + h * KEY_DIM + j0) =
                        __floats2half2_rn(a[h][i].x * inv, a[h][i].y * inv);
            }
        }
    } else {
        const float inv = 1.0f / NN_;
        #pragma unroll
        for (int i = 0; i < 7; i++) {
            int j0 = 2 * lane + 64 * i;
            if (j0 < KEY_DIM) {
                __half2 v = __floats2half2_rn(a[0][i].x * inv, a[0][i].y * inv);
                #pragma unroll
                for (int h = 0; h < 4; h++)
                    *(__half2*)(wsp + h * KEY_DIM + j0) = v;
            }
        }
    }
}

// ---------------------------------------------------------------------------
// LayerNorm epilogue (frozen)
// ---------------------------------------------------------------------------
__global__ __launch_bounds__(128)
void ln_kernel(const float* __restrict__ X,
               const float* __restrict__ node, const float* __restrict__ ntime,
               const float* __restrict__ br, const float* __restrict__ gamma,
               const float* __restrict__ beta, float* __restrict__ out) {
    int b = blockIdx.x;
    int t = threadIdx.x;
    long base = (long)b * OUT_DIM;
    const float* nd = node + (long)b * NODE_DIM;
    const float* tm = ntime + (long)b * TIME_DIM;

    float r0 = nd[t];
    float r1 = (t + 128 < NODE_DIM) ? nd[t + 128] : tm[t + 128 - NODE_DIM];
    float v0 = X[base + t] + br[t] + r0;
    float v1 = X[base + t + 128] + br[t + 128] + r1;
    float v2 = 0.f;
    if (t < OUT_DIM - 256)
        v2 = X[base + t + 256] + br[t + 256] + tm[t + 256 - NODE_DIM];

    float s  = v0 + v1 + v2;
    float ss = v0 * v0 + v1 * v1 + v2 * v2;
    #pragma unroll
    for (int o = 16; o > 0; o >>= 1) {
        s  += __shfl_xor_sync(0xffffffffu, s, o);
        ss += __shfl_xor_sync(0xffffffffu, ss, o);
    }
    __shared__ float rs[4], rss[4], bc[2];
    if ((t & 31) == 0) { rs[t >> 5] = s; rss[t >> 5] = ss; }
    __syncthreads();
    if (t == 0) {
        float S  = rs[0] + rs[1] + rs[2] + rs[3];
        float SS = rss[0] + rss[1] + rss[2] + rss[3];
        float mu = S / OUT_DIM;
        float var = SS / OUT_DIM - mu * mu;
        bc[0] = mu;
        bc[1] = rsqrtf(var + EPS_LN);
    }
    __syncthreads();
    float mu = bc[0], rstd = bc[1];

    out[base + t]       = (v0 - mu) * rstd * gamma[t] + beta[t];
    out[base + t + 128] = (v1 - mu) * rstd * gamma[t + 128] + beta[t + 128];
    if (t < OUT_DIM - 256)
        out[base + t + 256] = (v2 - mu) * rstd * gamma[t + 256] + beta[t + 256];
}

// ---------------------------------------------------------------------------
// Launch
// ---------------------------------------------------------------------------
extern "C" void kernel_launch(void* const* d_in, const int* in_sizes, int n_in,
                              void* d_out, int out_size) {
    const float* node   = (const float*)d_in[0];
    const float* ntime  = (const float*)d_in[1];
    const float* nbN    = (const float*)d_in[2];
    const float* nbT    = (const float*)d_in[3];
    const float* nbE    = (const float*)d_in[4];
    const int*   masks  = (const int*)d_in[5];
    const float* Wq     = (const float*)d_in[6];
    const float* Wk     = (const float*)d_in[7];
    const float* Wv     = (const float*)d_in[8];
    const float* Wr     = (const float*)d_in[9];
    const float* br     = (const float*)d_in[10];
    const float* gamma  = (const float*)d_in[11];
    const float* beta   = (const float*)d_in[12];
    float* out = (float*)d_out;

    __half *QIN, *Q, *QW, *WS, *ATT, *hWq, *hWr, *Bt2, *Bt3;
    float *X;
    cudaGetSymbolAddress((void**)&QIN, g_QIN);
    cudaGetSymbolAddress((void**)&Q,   g_Q);
    cudaGetSymbolAddress((void**)&QW,  g_QW);
    cudaGetSymbolAddress((void**)&WS,  g_WS);
    cudaGetSymbolAddress((void**)&ATT, g_ATT);
    cudaGetSymbolAddress((void**)&X,   g_X);
    cudaGetSymbolAddress((void**)&hWq, g_Wq);
    cudaGetSymbolAddress((void**)&hWr, g_Wr);
    cudaGetSymbolAddress((void**)&Bt2, g_Bt2);
    cudaGetSymbolAddress((void**)&Bt3, g_Bt3);

    // 0/1. prep
    prep_w<<<(W3 + 255) / 256, 256>>>(Wq, Wr, Wk, Wv, hWq, hWr, Bt2, Bt3);
    prep_qin<<<(PQ + 255) / 256, 256>>>(node, ntime, QIN);

    // 2. Q = QIN @ Wq^T                       [16384,272], K=272
    gemm_fp16<272, 272, true><<<dim3(5, 128), 128>>>(
        QIN, OUT_DIM, hWq, OUT_DIM, Q, OUT_DIM, OUT_DIM, OUT_DIM);

    // 3. QW = Q @ Bt2^T (wide tile: BN=128)   [16384,1776], K=272 (profiled)
    gemm_wide<KEY_DIM, DH><<<dim3(14, 128), 256>>>(
        Q, OUT_DIM, Bt2, OUT_DIM, QW, HH * KEY_DIM, HH * KEY_DIM, OUT_DIM);

    // 4. Attention (single-pass warp-per-row, __expf)
    attn_kernel<<<BB / 4, 128>>>(nbN, nbT, nbE, masks, QW, WS);

    // 5. ATT = WS @ Bt3^T (block-diag)        [16384,272], K=1776
    gemm_fp16<DH, KEY_DIM, true><<<dim3(5, 128), 128>>>(
        WS, HH * KEY_DIM, Bt3, HH * KEY_DIM, ATT, OUT_DIM, OUT_DIM, HH * KEY_DIM);

    // 6. X = ATT @ Wr^T                       [16384,272], K=272
    gemm_fp16<272, 272, false><<<dim3(5, 128), 128>>>(
        ATT, OUT_DIM, hWr, OUT_DIM, X, OUT_DIM, OUT_DIM, OUT_DIM);

    // 7. out = LayerNorm(X + br + residual)
    ln_kernel<<<BB, 128>>>(X, node, ntime, br, gamma, beta, out);
}

// round 15
// speedup vs baseline: 1.0050x; 1.0050x over previous
#include <cuda_runtime.h>
#include <cuda_fp16.h>
#include <math.h>
#include <stdint.h>

// Problem constants
#define BB 16384
#define NN_ 20
#define NODE_DIM 172
#define EDGE_DIM 172
#define TIME_DIM 100
#define HH 4
#define OUT_DIM 272
#define KEY_DIM 444
#define DH 68
#define EPS_LN 1e-5f
#define SCALE_QK 0.12126781251816648f   // 68^-0.5

// Scratch (device globals)
__device__ __half g_QIN[BB * OUT_DIM];
__device__ __half g_Q[BB * OUT_DIM];
__device__ __half g_QW[BB * HH * KEY_DIM];        // [B,1776]
__device__ __half g_WS[BB * HH * KEY_DIM];        // [B,1776]
__device__ __half g_ATT[BB * OUT_DIM];
__device__ float  g_X[BB * OUT_DIM];
__device__ __half g_Wq[OUT_DIM * OUT_DIM];
__device__ __half g_Wr[OUT_DIM * OUT_DIM];
__device__ __half g_Bt2[HH * KEY_DIM * OUT_DIM];  // [1776,272] block-diag scale*Wk^T
__device__ __half g_Bt3[OUT_DIM * HH * KEY_DIM];  // [272,1776] block-diag Wv

// ---------------------------------------------------------------------------
// helpers
// ---------------------------------------------------------------------------
__device__ __forceinline__ void mma_fp16(float (&c)[4], const uint32_t (&a)[4],
                                         const uint32_t (&b)[2]) {
    asm volatile(
        "mma.sync.aligned.m16n8k16.row.col.f32.f16.f16.f32 "
        "{%0,%1,%2,%3}, {%4,%5,%6,%7}, {%8,%9}, {%0,%1,%2,%3};"
        : "+f"(c[0]), "+f"(c[1]), "+f"(c[2]), "+f"(c[3])
        : "r"(a[0]), "r"(a[1]), "r"(a[2]), "r"(a[3]), "r"(b[0]), "r"(b[1]));
}

__device__ __forceinline__ void ldsm_x4(uint32_t (&r)[4], uint32_t addr) {
    asm volatile("ldmatrix.sync.aligned.m8n8.x4.shared.b16 {%0,%1,%2,%3}, [%4];"
        : "=r"(r[0]), "=r"(r[1]), "=r"(r[2]), "=r"(r[3]) : "r"(addr));
}

__device__ __forceinline__ void cp16z(uint32_t d, const void* s, int sz) {
    asm volatile("cp.async.cg.shared.global [%0], [%1], 16, %2;"
                 :: "r"(d), "l"(s), "r"(sz));
}
__device__ __forceinline__ void cp_commit() {
    asm volatile("cp.async.commit_group;");
}
template<int W> __device__ __forceinline__ void cp_wait() {
    asm volatile("cp.async.wait_group %0;" :: "n"(W));
}

// ---------------------------------------------------------------------------
// Single prep kernel: Wq->h, Wr->h, Bt2, Bt3, QIN concat (one launch)
// ---------------------------------------------------------------------------
#define PW (OUT_DIM * OUT_DIM)              // 73984
#define PB (HH * KEY_DIM * OUT_DIM)         // 483072
#define PQ (BB * OUT_DIM)                   // 4456448
#define N0 PW
#define N1 (N0 + PW)
#define N2 (N1 + PB)
#define N3 (N2 + PB)
#define N4 (N3 + PQ)

__global__ void prep_all(const float* __restrict__ Wq, const float* __restrict__ Wr,
                         const float* __restrict__ Wk, const float* __restrict__ Wv,
                         const float* __restrict__ node, const float* __restrict__ ntime,
                         __half* __restrict__ dWq, __half* __restrict__ dWr,
                         __half* __restrict__ dB2, __half* __restrict__ dB3,
                         __half* __restrict__ dQIN) {
    long idx = (long)blockIdx.x * 256 + threadIdx.x;
    if (idx < N0) {
        dWq[idx] = __float2half_rn(Wq[idx]);
    } else if (idx < N1) {
        long i = idx - N0;
        dWr[i] = __float2half_rn(Wr[i]);
    } else if (idx < N2) {
        long i = idx - N1;
        int n = (int)(i / OUT_DIM), k = (int)(i - (long)n * OUT_DIM);
        int h = n / KEY_DIM, j = n - h * KEY_DIM;
        float v = 0.f;
        if (k >= h * DH && k < h * DH + DH)
            v = SCALE_QK * Wk[k * KEY_DIM + j];
        dB2[i] = __float2half_rn(v);
    } else if (idx < N3) {
        long i = idx - N2;
        int n = (int)(i / (HH * KEY_DIM)), k = (int)(i - (long)n * (HH * KEY_DIM));
        int h = n / DH;
        float v = 0.f;
        if (k >= h * KEY_DIM && k < h * KEY_DIM + KEY_DIM)
            v = Wv[n * KEY_DIM + (k - h * KEY_DIM)];
        dB3[i] = __float2half_rn(v);
    } else if (idx < N4) {
        long i = idx - N3;
        int b = (int)(i / OUT_DIM), o = (int)(i - (long)b * OUT_DIM);
        float v = (o < NODE_DIM) ? node[(long)b * NODE_DIM + o]
                                 : ntime[(long)b * TIME_DIM + (o - NODE_DIM)];
        dQIN[i] = __float2half_rn(v);
    }
}

// ---------------------------------------------------------------------------
// fp16 TC GEMM (cp.async 3-stage + ldmatrix):  C[m,n] = sum_k A[m,k]*Bt[n,k]
// BM=128, BN=64, BK=32, warp tile 64x32, mma.m16n8k16, fp32 accumulate.
// ---------------------------------------------------------------------------
template<int NPH, int KPH, bool HALF_C>
__global__ __launch_bounds__(128)
void gemm_fp16(const __half* __restrict__ A, int lda,
               const __half* __restrict__ Bt, int ldb,
               void* __restrict__ Cv, int ldc, int N, int K) {
    __shared__ __half As[3][128][40];
    __shared__ __half Bs[3][64][40];

    const int t = threadIdx.x;
    const int warp = t >> 5, lane = t & 31;
    const int wm = (warp >> 1) * 64, wn = (warp & 1) * 32;
    const int gid = lane >> 2, tig = lane & 3;
    const long m0 = (long)blockIdx.y * 128;
    const int n0 = blockIdx.x * 64;

    const uint32_t as_base = (uint32_t)__cvta_generic_to_shared(&As[0][0][0]);
    const uint32_t bs_base = (uint32_t)__cvta_generic_to_shared(&Bs[0][0][0]);

    int h_lo = n0 / NPH;
    int n_last = min(n0 + 64, N) - 1;
    int h_hi = n_last / NPH;
    int klo = (h_lo * KPH) & ~31;
    int khi = min((((h_hi + 1) * KPH) + 31) & ~31, (K + 31) & ~31);
    int nstage = (khi - klo) >> 5;

    float acc[4][4][4];
    #pragma unroll
    for (int mi = 0; mi < 4; mi++)
        #pragma unroll
        for (int ni = 0; ni < 4; ni++)
            #pragma unroll
            for (int q = 0; q < 4; q++) acc[mi][ni][q] = 0.f;

    auto load_stage = [&](int kk, int buf) {
        #pragma unroll
        for (int i = 0; i < 4; i++) {
            int id = i * 128 + t;
            int r = id >> 2, seg = (id & 3) * 8;
            int col = kk + seg;
            cp16z(as_base + (uint32_t)(buf * 5120 + r * 40 + seg) * 2,
                  A + (m0 + r) * lda + min(col, K - 8),
                  col < K ? 16 : 0);
        }
        #pragma unroll
        for (int i = 0; i < 2; i++) {
            int id = i * 128 + t;
            int r = id >> 2, seg = (id & 3) * 8;
            int col = kk + seg;
            int rr = n0 + r;
            cp16z(bs_base + (uint32_t)(buf * 2560 + r * 40 + seg) * 2,
                  Bt + (long)min(rr, N - 1) * ldb + min(col, K - 8),
                  (rr < N && col < K) ? 16 : 0);
        }
    };

    auto compute = [&](int buf) {
        const int lr = lane & 7, sel = lane >> 3;
        #pragma unroll
        for (int ks = 0; ks < 32; ks += 16) {
            uint32_t af[4][4];
            #pragma unroll
            for (int mi = 0; mi < 4; mi++) {
                uint32_t addr = as_base + 2u * (uint32_t)(buf * 5120 +
                    (wm + mi * 16 + (sel & 1) * 8 + lr) * 40 + ks + (sel >> 1) * 8);
                ldsm_x4(af[mi], addr);
            }
            uint32_t bp[2][4];
            #pragma unroll
            for (int p = 0; p < 2; p++) {
                uint32_t addr = bs_base + 2u * (uint32_t)(buf * 2560 +
                    (wn + p * 16 + (sel >> 1) * 8 + lr) * 40 + ks + (sel & 1) * 8);
                ldsm_x4(bp[p], addr);
            }
            #pragma unroll
            for (int ni = 0; ni < 4; ni++) {
                uint32_t bf[2] = { bp[ni >> 1][(ni & 1) * 2],
                                   bp[ni >> 1][(ni & 1) * 2 + 1] };
                #pragma unroll
                for (int mi = 0; mi < 4; mi++)
                    mma_fp16(acc[mi][ni], af[mi], bf);
            }
        }
    };

    load_stage(klo, 0);
    cp_commit();
    if (nstage > 1) { load_stage(klo + 32, 1); cp_commit(); }

    int buf = 0;
    for (int s = 0; s < nstage; s++) {
        if (s + 2 < nstage) {
            load_stage(klo + (s + 2) * 32, (s + 2) % 3);
            cp_commit();
            cp_wait<2>();
        } else if (s + 1 < nstage) {
            cp_wait<1>();
        } else {
            cp_wait<0>();
        }
        __syncthreads();
        compute(buf);
        buf = (buf + 1) % 3;
        __syncthreads();
    }

    #pragma unroll
    for (int mi = 0; mi < 4; mi++)
        #pragma unroll
        for (int ni = 0; ni < 4; ni++) {
            long r = m0 + wm + mi * 16 + gid;
            int cn = n0 + wn + ni * 8 + tig * 2;
            if (cn < N) {
                if (HALF_C) {
                    __half* C = (__half*)Cv;
                    *(__half2*)(C + r * ldc + cn) =
                        __floats2half2_rn(acc[mi][ni][0], acc[mi][ni][1]);
                    *(__half2*)(C + (r + 8) * ldc + cn) =
                        __floats2half2_rn(acc[mi][ni][2], acc[mi][ni][3]);
                } else {
                    float* C = (float*)Cv;
                    *(float2*)(C + r * ldc + cn) =
                        make_float2(acc[mi][ni][0], acc[mi][ni][1]);
                    *(float2*)(C + (r + 8) * ldc + cn) =
                        make_float2(acc[mi][ni][2], acc[mi][ni][3]);
                }
            }
        }
}

// ---------------------------------------------------------------------------
// Warp-per-row SINGLE-PASS attention (frozen; __expf)
// ---------------------------------------------------------------------------
__device__ __forceinline__ float2 load_kv2(const float* pN, const float* pE,
                                           const float* pT, int j0) {
    if (j0 < NODE_DIM) return __ldg((const float2*)(pN + j0));
    if (j0 < NODE_DIM + EDGE_DIM) return __ldg((const float2*)(pE + (j0 - NODE_DIM)));
    if (j0 < KEY_DIM) return __ldg((const float2*)(pT + (j0 - NODE_DIM - EDGE_DIM)));
    return make_float2(0.f, 0.f);
}

__global__ __launch_bounds__(128, 4)
void attn_kernel(const float* __restrict__ nbN,
                 const float* __restrict__ nbT,
                 const float* __restrict__ nbE,
                 const int*   __restrict__ masks,
                 const __half* __restrict__ QW,
                 __half* __restrict__ WS) {
    const int lane = threadIdx.x & 31;
    const int warp = threadIdx.x >> 5;
    const long b = (long)blockIdx.x * 4 + warp;

    int mk = (lane < NN_) ? masks[b * NN_ + lane] : 0;
    unsigned bal = __ballot_sync(0xffffffffu, (lane < NN_) && (mk != 0));
    int nv = __popc(bal);
    const bool uni = (nv == 0);
    int map = uni ? lane : __fns(bal, 0, lane + 1);
    if (uni) nv = NN_;

    uint32_t qh[4][7];
    if (!uni) {
        const __half* qp = QW + b * (HH * KEY_DIM);
        #pragma unroll
        for (int h = 0; h < 4; h++)
            #pragma unroll
            for (int i = 0; i < 7; i++) {
                int j0 = 2 * lane + 64 * i;
                qh[h][i] = (j0 < KEY_DIM)
                    ? __ldg((const uint32_t*)(qp + h * KEY_DIM + j0)) : 0u;
            }
    }

    float2 a[4][7];
    #pragma unroll
    for (int h = 0; h < 4; h++)
        #pragma unroll
        for (int i = 0; i < 7; i++) a[h][i] = make_float2(0.f, 0.f);
    float m[4] = {-3e38f, -3e38f, -3e38f, -3e38f};
    float sum[4] = {0.f, 0.f, 0.f, 0.f};

    for (int n = 0; n < nv; n++) {
        int src = __shfl_sync(0xffffffffu, map, n);
        const float* pN = nbN + (b * NN_ + src) * NODE_DIM;
        const float* pE = nbE + (b * NN_ + src) * EDGE_DIM;
        const float* pT = nbT + (b * NN_ + src) * TIME_DIM;
        float2 kv[7];
        #pragma unroll
        for (int i = 0; i < 7; i++) kv[i] = load_kv2(pN, pE, pT, 2 * lane + 64 * i);

        if (!uni) {
            float s0 = 0.f, s1 = 0.f, s2 = 0.f, s3 = 0.f;
            #pragma unroll
            for (int i = 0; i < 7; i++) {
                float2 q0 = __half22float2(*(const __half2*)&qh[0][i]);
                float2 q1 = __half22float2(*(const __half2*)&qh[1][i]);
                float2 q2 = __half22float2(*(const __half2*)&qh[2][i]);
                float2 q3 = __half22float2(*(const __half2*)&qh[3][i]);
                s0 = fmaf(kv[i].x, q0.x, fmaf(kv[i].y, q0.y, s0));
                s1 = fmaf(kv[i].x, q1.x, fmaf(kv[i].y, q1.y, s1));
                s2 = fmaf(kv[i].x, q2.x, fmaf(kv[i].y, q2.y, s2));
                s3 = fmaf(kv[i].x, q3.x, fmaf(kv[i].y, q3.y, s3));
            }
            #pragma unroll
            for (int o = 16; o; o >>= 1) {
                s0 += __shfl_xor_sync(0xffffffffu, s0, o);
                s1 += __shfl_xor_sync(0xffffffffu, s1, o);
                s2 += __shfl_xor_sync(0xffffffffu, s2, o);
                s3 += __shfl_xor_sync(0xffffffffu, s3, o);
            }
            float sh[4] = {s0, s1, s2, s3};

            #pragma unroll
            for (int h = 0; h < 4; h++) {
                float s = sh[h];
                if (s > m[h]) {
                    float c = __expf(m[h] - s);
                    sum[h] = sum[h] * c + 1.f;
                    m[h] = s;
                    #pragma unroll
                    for (int i = 0; i < 7; i++) {
                        a[h][i].x = fmaf(a[h][i].x, c, kv[i].x);
                        a[h][i].y = fmaf(a[h][i].y, c, kv[i].y);
                    }
                } else {
                    float w = __expf(s - m[h]);
                    sum[h] += w;
                    #pragma unroll
                    for (int i = 0; i < 7; i++) {
                        a[h][i].x = fmaf(w, kv[i].x, a[h][i].x);
                        a[h][i].y = fmaf(w, kv[i].y, a[h][i].y);
                    }
                }
            }
        } else {
            #pragma unroll
            for (int i = 0; i < 7; i++) {
                a[0][i].x += kv[i].x;
                a[0][i].y += kv[i].y;
            }
        }
    }

    __half* wsp = WS + b * (HH * KEY_DIM);
    if (!uni) {
        #pragma unroll
        for (int h = 0; h < 4; h++) {
            float inv = 1.f / sum[h];
            #pragma unroll
            for (int i = 0; i < 7; i++) {
                int j0 = 2 * lane + 64 * i;
                if (j0 < KEY_DIM)
                    *(__half2*)(wsp + h * KEY_DIM + j0) =
                        __floats2half2_rn(a[h][i].x * inv, a[h][i].y * inv);
            }
        }
    } else {
        const float inv = 1.0f / NN_;
        #pragma unroll
        for (int i = 0; i < 7; i++) {
            int j0 = 2 * lane + 64 * i;
            if (j0 < KEY_DIM) {
                __half2 v = __floats2half2_rn(a[0][i].x * inv, a[0][i].y * inv);
                #pragma unroll
                for (int h = 0; h < 4; h++)
                    *(__half2*)(wsp + h * KEY_DIM + j0) = v;
            }
        }
    }
}

// ---------------------------------------------------------------------------
// LayerNorm epilogue (frozen)
// ---------------------------------------------------------------------------
__global__ __launch_bounds__(128)
void ln_kernel(const float* __restrict__ X,
               const float* __restrict__ node, const float* __restrict__ ntime,
               const float* __restrict__ br, const float* __restrict__ gamma,
               const float* __restrict__ beta, float* __restrict__ out) {
    int b = blockIdx.x;
    int t = threadIdx.x;
    long base = (long)b * OUT_DIM;
    const float* nd = node + (long)b * NODE_DIM;
    const float* tm = ntime + (long)b * TIME_DIM;

    float r0 = nd[t];
    float r1 = (t + 128 < NODE_DIM) ? nd[t + 128] : tm[t + 128 - NODE_DIM];
    float v0 = X[base + t] + br[t] + r0;
    float v1 = X[base + t + 128] + br[t + 128] + r1;
    float v2 = 0.f;
    if (t < OUT_DIM - 256)
        v2 = X[base + t + 256] + br[t + 256] + tm[t + 256 - NODE_DIM];

    float s  = v0 + v1 + v2;
    float ss = v0 * v0 + v1 * v1 + v2 * v2;
    #pragma unroll
    for (int o = 16; o > 0; o >>= 1) {
        s  += __shfl_xor_sync(0xffffffffu, s, o);
        ss += __shfl_xor_sync(0xffffffffu, ss, o);
    }
    __shared__ float rs[4], rss[4], bc[2];
    if ((t & 31) == 0) { rs[t >> 5] = s; rss[t >> 5] = ss; }
    __syncthreads();
    if (t == 0) {
        float S  = rs[0] + rs[1] + rs[2] + rs[3];
        float SS = rss[0] + rss[1] + rss[2] + rss[3];
        float mu = S / OUT_DIM;
        float var = SS / OUT_DIM - mu * mu;
        bc[0] = mu;
        bc[1] = rsqrtf(var + EPS_LN);
    }
    __syncthreads();
    float mu = bc[0], rstd = bc[1];

    out[base + t]       = (v0 - mu) * rstd * gamma[t] + beta[t];
    out[base + t + 128] = (v1 - mu) * rstd * gamma[t + 128] + beta[t + 128];
    if (t < OUT_DIM - 256)
        out[base + t + 256] = (v2 - mu) * rstd * gamma[t + 256] + beta[t + 256];
}

// ---------------------------------------------------------------------------
// Launch: prep(0), gemm1(1), gemm2(2), attn(3, profiled), gemm5(4),
//         gemm6(5), ln(6) — 7 launches
// ---------------------------------------------------------------------------
extern "C" void kernel_launch(void* const* d_in, const int* in_sizes, int n_in,
                              void* d_out, int out_size) {
    const float* node   = (const float*)d_in[0];
    const float* ntime  = (const float*)d_in[1];
    const float* nbN    = (const float*)d_in[2];
    const float* nbT    = (const float*)d_in[3];
    const float* nbE    = (const float*)d_in[4];
    const int*   masks  = (const int*)d_in[5];
    const float* Wq     = (const float*)d_in[6];
    const float* Wk     = (const float*)d_in[7];
    const float* Wv     = (const float*)d_in[8];
    const float* Wr     = (const float*)d_in[9];
    const float* br     = (const float*)d_in[10];
    const float* gamma  = (const float*)d_in[11];
    const float* beta   = (const float*)d_in[12];
    float* out = (float*)d_out;

    __half *QIN, *Q, *QW, *WS, *ATT, *hWq, *hWr, *Bt2, *Bt3;
    float *X;
    cudaGetSymbolAddress((void**)&QIN, g_QIN);
    cudaGetSymbolAddress((void**)&Q,   g_Q);
    cudaGetSymbolAddress((void**)&QW,  g_QW);
    cudaGetSymbolAddress((void**)&WS,  g_WS);
    cudaGetSymbolAddress((void**)&ATT, g_ATT);
    cudaGetSymbolAddress((void**)&X,   g_X);
    cudaGetSymbolAddress((void**)&hWq, g_Wq);
    cudaGetSymbolAddress((void**)&hWr, g_Wr);
    cudaGetSymbolAddress((void**)&Bt2, g_Bt2);
    cudaGetSymbolAddress((void**)&Bt3, g_Bt3);

    // 0. prep (one launch)
    prep_all<<<(N4 + 255) / 256, 256>>>(Wq, Wr, Wk, Wv, node, ntime,
                                        hWq, hWr, Bt2, Bt3, QIN);

    // 1. Q = QIN @ Wq^T                       [16384,272], K=272
    gemm_fp16<272, 272, true><<<dim3(5, 128), 128>>>(
        QIN, OUT_DIM, hWq, OUT_DIM, Q, OUT_DIM, OUT_DIM, OUT_DIM);

    // 2. QW = Q @ Bt2^T (block-diag)          [16384,1776], K=272
    gemm_fp16<KEY_DIM, DH, true><<<dim3(28, 128), 128>>>(
        Q, OUT_DIM, Bt2, OUT_DIM, QW, HH * KEY_DIM, HH * KEY_DIM, OUT_DIM);

    // 3. Attention (single-pass warp-per-row, __expf) — profiled slot
    attn_kernel<<<BB / 4, 128>>>(nbN, nbT, nbE, masks, QW, WS);

    // 4. ATT = WS @ Bt3^T (block-diag)        [16384,272], K=1776
    gemm_fp16<DH, KEY_DIM, true><<<dim3(5, 128), 128>>>(
        WS, HH * KEY_DIM, Bt3, HH * KEY_DIM, ATT, OUT_DIM, OUT_DIM, HH * KEY_DIM);

    // 5. X = ATT @ Wr^T                       [16384,272], K=272
    gemm_fp16<272, 272, false><<<dim3(5, 128), 128>>>(
        ATT, OUT_DIM, hWr, OUT_DIM, X, OUT_DIM, OUT_DIM, OUT_DIM);

    // 6. out = LayerNorm(X + br + residual)
    ln_kernel<<<BB, 128>>>(X, node, ntime, br, gamma, beta, out);
}

// round 16
// speedup vs baseline: 1.0369x; 1.0317x over previous
#include <cuda_runtime.h>
#include <cuda_fp16.h>
#include <math.h>
#include <stdint.h>

// Problem constants
#define BB 16384
#define NN_ 20
#define NODE_DIM 172
#define EDGE_DIM 172
#define TIME_DIM 100
#define HH 4
#define OUT_DIM 272
#define KEY_DIM 444
#define DH 68
#define EPS_LN 1e-5f
#define SCALE_QK 0.12126781251816648f   // 68^-0.5

// Scratch (device globals)
__device__ __half g_QIN[BB * OUT_DIM];
__device__ __half g_Q[BB * OUT_DIM];
__device__ __half g_QW[BB * HH * KEY_DIM];        // [B,1776]
__device__ __half g_WS[BB * HH * KEY_DIM];        // [B,1776]
__device__ __half g_ATT[BB * OUT_DIM];
__device__ float  g_X[BB * OUT_DIM];
__device__ __half g_Wq[OUT_DIM * OUT_DIM];
__device__ __half g_Wr[OUT_DIM * OUT_DIM];
__device__ __half g_Bt2[HH * KEY_DIM * OUT_DIM];  // [1776,272] block-diag scale*Wk^T
__device__ __half g_Bt3[OUT_DIM * HH * KEY_DIM];  // [272,1776] block-diag Wv

// ---------------------------------------------------------------------------
// helpers
// ---------------------------------------------------------------------------
__device__ __forceinline__ void mma_fp16(float (&c)[4], const uint32_t (&a)[4],
                                         const uint32_t (&b)[2]) {
    asm volatile(
        "mma.sync.aligned.m16n8k16.row.col.f32.f16.f16.f32 "
        "{%0,%1,%2,%3}, {%4,%5,%6,%7}, {%8,%9}, {%0,%1,%2,%3};"
        : "+f"(c[0]), "+f"(c[1]), "+f"(c[2]), "+f"(c[3])
        : "r"(a[0]), "r"(a[1]), "r"(a[2]), "r"(a[3]), "r"(b[0]), "r"(b[1]));
}

__device__ __forceinline__ void ldsm_x4(uint32_t (&r)[4], uint32_t addr) {
    asm volatile("ldmatrix.sync.aligned.m8n8.x4.shared.b16 {%0,%1,%2,%3}, [%4];"
        : "=r"(r[0]), "=r"(r[1]), "=r"(r[2]), "=r"(r[3]) : "r"(addr));
}

__device__ __forceinline__ void cp16z(uint32_t d, const void* s, int sz) {
    asm volatile("cp.async.cg.shared.global [%0], [%1], 16, %2;"
                 :: "r"(d), "l"(s), "r"(sz));
}
__device__ __forceinline__ void cp_commit() {
    asm volatile("cp.async.commit_group;");
}
template<int W> __device__ __forceinline__ void cp_wait() {
    asm volatile("cp.async.wait_group %0;" :: "n"(W));
}

// ---------------------------------------------------------------------------
// Single prep kernel: Wq->h, Wr->h, Bt2, Bt3, QIN concat (one launch)
// ---------------------------------------------------------------------------
#define PW (OUT_DIM * OUT_DIM)              // 73984
#define PB (HH * KEY_DIM * OUT_DIM)         // 483072
#define PQ (BB * OUT_DIM)                   // 4456448
#define N0 PW
#define N1 (N0 + PW)
#define N2 (N1 + PB)
#define N3 (N2 + PB)
#define N4 (N3 + PQ)

__global__ void prep_all(const float* __restrict__ Wq, const float* __restrict__ Wr,
                         const float* __restrict__ Wk, const float* __restrict__ Wv,
                         const float* __restrict__ node, const float* __restrict__ ntime,
                         __half* __restrict__ dWq, __half* __restrict__ dWr,
                         __half* __restrict__ dB2, __half* __restrict__ dB3,
                         __half* __restrict__ dQIN) {
    long idx = (long)blockIdx.x * 256 + threadIdx.x;
    if (idx < N0) {
        dWq[idx] = __float2half_rn(Wq[idx]);
    } else if (idx < N1) {
        long i = idx - N0;
        dWr[i] = __float2half_rn(Wr[i]);
    } else if (idx < N2) {
        long i = idx - N1;
        int n = (int)(i / OUT_DIM), k = (int)(i - (long)n * OUT_DIM);
        int h = n / KEY_DIM, j = n - h * KEY_DIM;
        float v = 0.f;
        if (k >= h * DH && k < h * DH + DH)
            v = SCALE_QK * Wk[k * KEY_DIM + j];
        dB2[i] = __float2half_rn(v);
    } else if (idx < N3) {
        long i = idx - N2;
        int n = (int)(i / (HH * KEY_DIM)), k = (int)(i - (long)n * (HH * KEY_DIM));
        int h = n / DH;
        float v = 0.f;
        if (k >= h * KEY_DIM && k < h * KEY_DIM + KEY_DIM)
            v = Wv[n * KEY_DIM + (k - h * KEY_DIM)];
        dB3[i] = __float2half_rn(v);
    } else if (idx < N4) {
        long i = idx - N3;
        int b = (int)(i / OUT_DIM), o = (int)(i - (long)b * OUT_DIM);
        float v = (o < NODE_DIM) ? node[(long)b * NODE_DIM + o]
                                 : ntime[(long)b * TIME_DIM + (o - NODE_DIM)];
        dQIN[i] = __float2half_rn(v);
    }
}

// ---------------------------------------------------------------------------
// fp16 TC GEMM (cp.async 3-stage + ldmatrix):  C[m,n] = sum_k A[m,k]*Bt[n,k]
// BM=128, BN=64, BK=32, warp tile 64x32, mma.m16n8k16, fp32 accumulate.
// ---------------------------------------------------------------------------
template<int NPH, int KPH, bool HALF_C>
__global__ __launch_bounds__(128)
void gemm_fp16(const __half* __restrict__ A, int lda,
               const __half* __restrict__ Bt, int ldb,
               void* __restrict__ Cv, int ldc, int N, int K) {
    __shared__ __half As[3][128][40];
    __shared__ __half Bs[3][64][40];

    const int t = threadIdx.x;
    const int warp = t >> 5, lane = t & 31;
    const int wm = (warp >> 1) * 64, wn = (warp & 1) * 32;
    const int gid = lane >> 2, tig = lane & 3;
    const long m0 = (long)blockIdx.y * 128;
    const int n0 = blockIdx.x * 64;

    const uint32_t as_base = (uint32_t)__cvta_generic_to_shared(&As[0][0][0]);
    const uint32_t bs_base = (uint32_t)__cvta_generic_to_shared(&Bs[0][0][0]);

    int h_lo = n0 / NPH;
    int n_last = min(n0 + 64, N) - 1;
    int h_hi = n_last / NPH;
    int klo = (h_lo * KPH) & ~31;
    int khi = min((((h_hi + 1) * KPH) + 31) & ~31, (K + 31) & ~31);
    int nstage = (khi - klo) >> 5;

    float acc[4][4][4];
    #pragma unroll
    for (int mi = 0; mi < 4; mi++)
        #pragma unroll
        for (int ni = 0; ni < 4; ni++)
            #pragma unroll
            for (int q = 0; q < 4; q++) acc[mi][ni][q] = 0.f;

    auto load_stage = [&](int kk, int buf) {
        #pragma unroll
        for (int i = 0; i < 4; i++) {
            int id = i * 128 + t;
            int r = id >> 2, seg = (id & 3) * 8;
            int col = kk + seg;
            cp16z(as_base + (uint32_t)(buf * 5120 + r * 40 + seg) * 2,
                  A + (m0 + r) * lda + min(col, K - 8),
                  col < K ? 16 : 0);
        }
        #pragma unroll
        for (int i = 0; i < 2; i++) {
            int id = i * 128 + t;
            int r = id >> 2, seg = (id & 3) * 8;
            int col = kk + seg;
            int rr = n0 + r;
            cp16z(bs_base + (uint32_t)(buf * 2560 + r * 40 + seg) * 2,
                  Bt + (long)min(rr, N - 1) * ldb + min(col, K - 8),
                  (rr < N && col < K) ? 16 : 0);
        }
    };

    auto compute = [&](int buf) {
        const int lr = lane & 7, sel = lane >> 3;
        #pragma unroll
        for (int ks = 0; ks < 32; ks += 16) {
            uint32_t af[4][4];
            #pragma unroll
            for (int mi = 0; mi < 4; mi++) {
                uint32_t addr = as_base + 2u * (uint32_t)(buf * 5120 +
                    (wm + mi * 16 + (sel & 1) * 8 + lr) * 40 + ks + (sel >> 1) * 8);
                ldsm_x4(af[mi], addr);
            }
            uint32_t bp[2][4];
            #pragma unroll
            for (int p = 0; p < 2; p++) {
                uint32_t addr = bs_base + 2u * (uint32_t)(buf * 2560 +
                    (wn + p * 16 + (sel >> 1) * 8 + lr) * 40 + ks + (sel & 1) * 8);
                ldsm_x4(bp[p], addr);
            }
            #pragma unroll
            for (int ni = 0; ni < 4; ni++) {
                uint32_t bf[2] = { bp[ni >> 1][(ni & 1) * 2],
                                   bp[ni >> 1][(ni & 1) * 2 + 1] };
                #pragma unroll
                for (int mi = 0; mi < 4; mi++)
                    mma_fp16(acc[mi][ni], af[mi], bf);
            }
        }
    };

    load_stage(klo, 0);
    cp_commit();
    if (nstage > 1) { load_stage(klo + 32, 1); cp_commit(); }

    int buf = 0;
    for (int s = 0; s < nstage; s++) {
        if (s + 2 < nstage) {
            load_stage(klo + (s + 2) * 32, (s + 2) % 3);
            cp_commit();
            cp_wait<2>();
        } else if (s + 1 < nstage) {
            cp_wait<1>();
        } else {
            cp_wait<0>();
        }
        __syncthreads();
        compute(buf);
        buf = (buf + 1) % 3;
        __syncthreads();
    }

    #pragma unroll
    for (int mi = 0; mi < 4; mi++)
        #pragma unroll
        for (int ni = 0; ni < 4; ni++) {
            long r = m0 + wm + mi * 16 + gid;
            int cn = n0 + wn + ni * 8 + tig * 2;
            if (cn < N) {
                if (HALF_C) {
                    __half* C = (__half*)Cv;
                    *(__half2*)(C + r * ldc + cn) =
                        __floats2half2_rn(acc[mi][ni][0], acc[mi][ni][1]);
                    *(__half2*)(C + (r + 8) * ldc + cn) =
                        __floats2half2_rn(acc[mi][ni][2], acc[mi][ni][3]);
                } else {
                    float* C = (float*)Cv;
                    *(float2*)(C + r * ldc + cn) =
                        make_float2(acc[mi][ni][0], acc[mi][ni][1]);
                    *(float2*)(C + (r + 8) * ldc + cn) =
                        make_float2(acc[mi][ni][2], acc[mi][ni][3]);
                }
            }
        }
}

// ---------------------------------------------------------------------------
// Warp-per-row SINGLE-PASS attention. q-cache moved from registers to
// per-lane-private smem slots (written+read by the same thread: no sync;
// lane*4B stride: conflict-free LDS.32). Frees ~28 regs -> 5 CTAs/SM.
// ---------------------------------------------------------------------------
__device__ __forceinline__ float2 load_kv2(const float* pN, const float* pE,
                                           const float* pT, int j0) {
    if (j0 < NODE_DIM) return __ldg((const float2*)(pN + j0));
    if (j0 < NODE_DIM + EDGE_DIM) return __ldg((const float2*)(pE + (j0 - NODE_DIM)));
    if (j0 < KEY_DIM) return __ldg((const float2*)(pT + (j0 - NODE_DIM - EDGE_DIM)));
    return make_float2(0.f, 0.f);
}

__global__ __launch_bounds__(128, 5)
void attn_kernel(const float* __restrict__ nbN,
                 const float* __restrict__ nbT,
                 const float* __restrict__ nbE,
                 const int*   __restrict__ masks,
                 const __half* __restrict__ QW,
                 __half* __restrict__ WS) {
    __shared__ uint32_t qs[4][28][32];    // [warp][h*7+i][lane] = 14336 B

    const int lane = threadIdx.x & 31;
    const int warp = threadIdx.x >> 5;
    const long b = (long)blockIdx.x * 4 + warp;

    int mk = (lane < NN_) ? masks[b * NN_ + lane] : 0;
    unsigned bal = __ballot_sync(0xffffffffu, (lane < NN_) && (mk != 0));
    int nv = __popc(bal);
    const bool uni = (nv == 0);
    int map = uni ? lane : __fns(bal, 0, lane + 1);
    if (uni) nv = NN_;

    // q cache -> smem (per-lane-private slots; no synchronization needed)
    if (!uni) {
        const __half* qp = QW + b * (HH * KEY_DIM);
        #pragma unroll
        for (int h = 0; h < 4; h++)
            #pragma unroll
            for (int i = 0; i < 7; i++) {
                int j0 = 2 * lane + 64 * i;
                qs[warp][h * 7 + i][lane] = (j0 < KEY_DIM)
                    ? __ldg((const uint32_t*)(qp + h * KEY_DIM + j0)) : 0u;
            }
    }

    float2 a[4][7];
    #pragma unroll
    for (int h = 0; h < 4; h++)
        #pragma unroll
        for (int i = 0; i < 7; i++) a[h][i] = make_float2(0.f, 0.f);
    float m[4] = {-3e38f, -3e38f, -3e38f, -3e38f};
    float sum[4] = {0.f, 0.f, 0.f, 0.f};

    for (int n = 0; n < nv; n++) {
        int src = __shfl_sync(0xffffffffu, map, n);
        const float* pN = nbN + (b * NN_ + src) * NODE_DIM;
        const float* pE = nbE + (b * NN_ + src) * EDGE_DIM;
        const float* pT = nbT + (b * NN_ + src) * TIME_DIM;
        float2 kv[7];
        #pragma unroll
        for (int i = 0; i < 7; i++) kv[i] = load_kv2(pN, pE, pT, 2 * lane + 64 * i);

        if (!uni) {
            float s0 = 0.f, s1 = 0.f, s2 = 0.f, s3 = 0.f;
            #pragma unroll
            for (int i = 0; i < 7; i++) {
                uint32_t u0 = qs[warp][0 * 7 + i][lane];
                uint32_t u1 = qs[warp][1 * 7 + i][lane];
                uint32_t u2 = qs[warp][2 * 7 + i][lane];
                uint32_t u3 = qs[warp][3 * 7 + i][lane];
                float2 q0 = __half22float2(*(const __half2*)&u0);
                float2 q1 = __half22float2(*(const __half2*)&u1);
                float2 q2 = __half22float2(*(const __half2*)&u2);
                float2 q3 = __half22float2(*(const __half2*)&u3);
                s0 = fmaf(kv[i].x, q0.x, fmaf(kv[i].y, q0.y, s0));
                s1 = fmaf(kv[i].x, q1.x, fmaf(kv[i].y, q1.y, s1));
                s2 = fmaf(kv[i].x, q2.x, fmaf(kv[i].y, q2.y, s2));
                s3 = fmaf(kv[i].x, q3.x, fmaf(kv[i].y, q3.y, s3));
            }
            #pragma unroll
            for (int o = 16; o; o >>= 1) {
                s0 += __shfl_xor_sync(0xffffffffu, s0, o);
                s1 += __shfl_xor_sync(0xffffffffu, s1, o);
                s2 += __shfl_xor_sync(0xffffffffu, s2, o);
                s3 += __shfl_xor_sync(0xffffffffu, s3, o);
            }
            float sh[4] = {s0, s1, s2, s3};

            #pragma unroll
            for (int h = 0; h < 4; h++) {
                float s = sh[h];
                if (s > m[h]) {
                    float c = __expf(m[h] - s);
                    sum[h] = sum[h] * c + 1.f;
                    m[h] = s;
                    #pragma unroll
                    for (int i = 0; i < 7; i++) {
                        a[h][i].x = fmaf(a[h][i].x, c, kv[i].x);
                        a[h][i].y = fmaf(a[h][i].y, c, kv[i].y);
                    }
                } else {
                    float w = __expf(s - m[h]);
                    sum[h] += w;
                    #pragma unroll
                    for (int i = 0; i < 7; i++) {
                        a[h][i].x = fmaf(w, kv[i].x, a[h][i].x);
                        a[h][i].y = fmaf(w, kv[i].y, a[h][i].y);
                    }
                }
            }
        } else {
            #pragma unroll
            for (int i = 0; i < 7; i++) {
                a[0][i].x += kv[i].x;
                a[0][i].y += kv[i].y;
            }
        }
    }

    __half* wsp = WS + b * (HH * KEY_DIM);
    if (!uni) {
        #pragma unroll
        for (int h = 0; h < 4; h++) {
            float inv = 1.f / sum[h];
            #pragma unroll
            for (int i = 0; i < 7; i++) {
                int j0 = 2 * lane + 64 * i;
                if (j0 < KEY_DIM)
                    *(__half2*)(wsp + h * KEY_DIM + j0) =
                        __floats2half2_rn(a[h][i].x * inv, a[h][i].y * inv);
            }
        }
    } else {
        const float inv = 1.0f / NN_;
        #pragma unroll
        for (int i = 0; i < 7; i++) {
            int j0 = 2 * lane + 64 * i;
            if (j0 < KEY_DIM) {
                __half2 v = __floats2half2_rn(a[0][i].x * inv, a[0][i].y * inv);
                #pragma unroll
                for (int h = 0; h < 4; h++)
                    *(__half2*)(wsp + h * KEY_DIM + j0) = v;
            }
        }
    }
}

// ---------------------------------------------------------------------------
// LayerNorm epilogue (frozen)
// ---------------------------------------------------------------------------
__global__ __launch_bounds__(128)
void ln_kernel(const float* __restrict__ X,
               const float* __restrict__ node, const float* __restrict__ ntime,
               const float* __restrict__ br, const float* __restrict__ gamma,
               const float* __restrict__ beta, float* __restrict__ out) {
    int b = blockIdx.x;
    int t = threadIdx.x;
    long base = (long)b * OUT_DIM;
    const float* nd = node + (long)b * NODE_DIM;
    const float* tm = ntime + (long)b * TIME_DIM;

    float r0 = nd[t];
    float r1 = (t + 128 < NODE_DIM) ? nd[t + 128] : tm[t + 128 - NODE_DIM];
    float v0 = X[base + t] + br[t] + r0;
    float v1 = X[base + t + 128] + br[t + 128] + r1;
    float v2 = 0.f;
    if (t < OUT_DIM - 256)
        v2 = X[base + t + 256] + br[t + 256] + tm[t + 256 - NODE_DIM];

    float s  = v0 + v1 + v2;
    float ss = v0 * v0 + v1 * v1 + v2 * v2;
    #pragma unroll
    for (int o = 16; o > 0; o >>= 1) {
        s  += __shfl_xor_sync(0xffffffffu, s, o);
        ss += __shfl_xor_sync(0xffffffffu, ss, o);
    }
    __shared__ float rs[4], rss[4], bc[2];
    if ((t & 31) == 0) { rs[t >> 5] = s; rss[t >> 5] = ss; }
    __syncthreads();
    if (t == 0) {
        float S  = rs[0] + rs[1] + rs[2] + rs[3];
        float SS = rss[0] + rss[1] + rss[2] + rss[3];
        float mu = S / OUT_DIM;
        float var = SS / OUT_DIM - mu * mu;
        bc[0] = mu;
        bc[1] = rsqrtf(var + EPS_LN);
    }
    __syncthreads();
    float mu = bc[0], rstd = bc[1];

    out[base + t]       = (v0 - mu) * rstd * gamma[t] + beta[t];
    out[base + t + 128] = (v1 - mu) * rstd * gamma[t + 128] + beta[t + 128];
    if (t < OUT_DIM - 256)
        out[base + t + 256] = (v2 - mu) * rstd * gamma[t + 256] + beta[t + 256];
}

// ---------------------------------------------------------------------------
// Launch: prep(0), gemm1(1), gemm2(2), attn(3, profiled), gemm5(4),
//         gemm6(5), ln(6)
// ---------------------------------------------------------------------------
extern "C" void kernel_launch(void* const* d_in, const int* in_sizes, int n_in,
                              void* d_out, int out_size) {
    const float* node   = (const float*)d_in[0];
    const float* ntime  = (const float*)d_in[1];
    const float* nbN    = (const float*)d_in[2];
    const float* nbT    = (const float*)d_in[3];
    const float* nbE    = (const float*)d_in[4];
    const int*   masks  = (const int*)d_in[5];
    const float* Wq     = (const float*)d_in[6];
    const float* Wk     = (const float*)d_in[7];
    const float* Wv     = (const float*)d_in[8];
    const float* Wr     = (const float*)d_in[9];
    const float* br     = (const float*)d_in[10];
    const float* gamma  = (const float*)d_in[11];
    const float* beta   = (const float*)d_in[12];
    float* out = (float*)d_out;

    __half *QIN, *Q, *QW, *WS, *ATT, *hWq, *hWr, *Bt2, *Bt3;
    float *X;
    cudaGetSymbolAddress((void**)&QIN, g_QIN);
    cudaGetSymbolAddress((void**)&Q,   g_Q);
    cudaGetSymbolAddress((void**)&QW,  g_QW);
    cudaGetSymbolAddress((void**)&WS,  g_WS);
    cudaGetSymbolAddress((void**)&ATT, g_ATT);
    cudaGetSymbolAddress((void**)&X,   g_X);
    cudaGetSymbolAddress((void**)&hWq, g_Wq);
    cudaGetSymbolAddress((void**)&hWr, g_Wr);
    cudaGetSymbolAddress((void**)&Bt2, g_Bt2);
    cudaGetSymbolAddress((void**)&Bt3, g_Bt3);

    // 0. prep (one launch)
    prep_all<<<(N4 + 255) / 256, 256>>>(Wq, Wr, Wk, Wv, node, ntime,
                                        hWq, hWr, Bt2, Bt3, QIN);

    // 1. Q = QIN @ Wq^T                       [16384,272], K=272
    gemm_fp16<272, 272, true><<<dim3(5, 128), 128>>>(
        QIN, OUT_DIM, hWq, OUT_DIM, Q, OUT_DIM, OUT_DIM, OUT_DIM);

    // 2. QW = Q @ Bt2^T (block-diag)          [16384,1776], K=272
    gemm_fp16<KEY_DIM, DH, true><<<dim3(28, 128), 128>>>(
        Q, OUT_DIM, Bt2, OUT_DIM, QW, HH * KEY_DIM, HH * KEY_DIM, OUT_DIM);

    // 3. Attention (single-pass warp-per-row, smem q-cache, 5 CTAs/SM)
    attn_kernel<<<BB / 4, 128>>>(nbN, nbT, nbE, masks, QW, WS);

    // 4. ATT = WS @ Bt3^T (block-diag)        [16384,272], K=1776
    gemm_fp16<DH, KEY_DIM, true><<<dim3(5, 128), 128>>>(
        WS, HH * KEY_DIM, Bt3, HH * KEY_DIM, ATT, OUT_DIM, OUT_DIM, HH * KEY_DIM);

    // 5. X = ATT @ Wr^T                       [16384,272], K=272
    gemm_fp16<272, 272, false><<<dim3(5, 128), 128>>>(
        ATT, OUT_DIM, hWr, OUT_DIM, X, OUT_DIM, OUT_DIM, OUT_DIM);

    // 6. out = LayerNorm(X + br + residual)
    ln_kernel<<<BB, 128>>>(X, node, ntime, br, gamma, beta, out);
}